// round 5
// baseline (speedup 1.0000x reference)
#include <cuda_runtime.h>
#include <cstdint>

// D_FEAT = 64 floats = 16 float4 per row
#define D4 16
#define CHUNK_SHIFT 4   // 16 chunks of 4 floats per edge
#define CHUNK_MASK 15

__device__ int g_idx_is_32;   // 1 if edge_index is int32 on device, 0 if int64

__global__ void detect_idx_dtype_kernel(const unsigned int* __restrict__ ei_words) {
    // Interpret first 16 putative int64 entries; int64 node ids < 50000 have
    // zero high words. If any high word is nonzero, data must be int32.
    int is32 = 0;
    for (int i = 0; i < 16; i++) {
        if (ei_words[2 * i + 1] != 0u) is32 = 1;
    }
    g_idx_is_32 = is32;
}

__global__ void init_zero_kernel(float4* __restrict__ out, int n4) {
    int i = blockIdx.x * blockDim.x + threadIdx.x;
    if (i < n4) out[i] = make_float4(0.f, 0.f, 0.f, 0.f);
}

__global__ void scatter_kernel(const float4* __restrict__ x_sum,
                               const float4* __restrict__ x_prod,
                               const void* __restrict__ edge_index,
                               float* __restrict__ out_sum,
                               float* __restrict__ out_logprod,
                               int n_edges) {
    int gid = blockIdx.x * blockDim.x + threadIdx.x;
    int e = gid >> CHUNK_SHIFT;
    if (e >= n_edges) return;
    int c = gid & CHUNK_MASK;

    int s, d;
    if (g_idx_is_32) {
        const int* ei = (const int*)edge_index;
        s = ei[e];
        d = ei[n_edges + e];
    } else {
        const long long* ei = (const long long*)edge_index;
        s = (int)ei[e];
        d = (int)ei[n_edges + e];
    }

    // Gather: 16 consecutive threads read 16 consecutive float4 = 256B row, coalesced.
    float4 ms = x_sum[s * D4 + c];
    float4 mp = x_prod[s * D4 + c];

    float* os = out_sum + d * 64 + c * 4;
    atomicAdd(os + 0, ms.x);
    atomicAdd(os + 1, ms.y);
    atomicAdd(os + 2, ms.z);
    atomicAdd(os + 3, ms.w);

    float* op = out_logprod + d * 64 + c * 4;
    atomicAdd(op + 0, __logf(mp.x));
    atomicAdd(op + 1, __logf(mp.y));
    atomicAdd(op + 2, __logf(mp.z));
    atomicAdd(op + 3, __logf(mp.w));
}

__global__ void finalize_exp_kernel(float4* __restrict__ out_logprod, int n4) {
    int i = blockIdx.x * blockDim.x + threadIdx.x;
    if (i < n4) {
        float4 v = out_logprod[i];
        out_logprod[i] = make_float4(__expf(v.x), __expf(v.y), __expf(v.z), __expf(v.w));
    }
}

extern "C" void kernel_launch(void* const* d_in, const int* in_sizes, int n_in,
                              void* d_out, int out_size) {
    const float4* x_sum  = (const float4*)d_in[0];
    const float4* x_prod = (const float4*)d_in[1];
    const void*   ei     = d_in[2];

    const int n_nodes = in_sizes[0] / 64;        // 50000
    const int n_edges = in_sizes[2] / 2;         // 800000
    const int nd      = n_nodes * 64;            // 3.2M floats per half

    float* out_sum     = (float*)d_out;          // [N, 64]
    float* out_logprod = (float*)d_out + nd;     // [N, 64]

    // 0) detect index dtype (int32 vs int64) — deterministic for fixed input
    detect_idx_dtype_kernel<<<1, 1>>>((const unsigned int*)ei);

    // 1) zero both halves (6.4M floats = 1.6M float4)
    {
        int n4 = (2 * nd) / 4;
        int threads = 256;
        int blocks = (n4 + threads - 1) / threads;
        init_zero_kernel<<<blocks, threads>>>((float4*)d_out, n4);
    }

    // 2) scatter: one thread per (edge, 4-feature chunk) = E*16 threads
    {
        long long total = (long long)n_edges << CHUNK_SHIFT;  // 12.8M
        int threads = 256;
        int blocks = (int)((total + threads - 1) / threads);
        scatter_kernel<<<blocks, threads>>>(x_sum, x_prod, ei,
                                            out_sum, out_logprod, n_edges);
    }

    // 3) exp-finalize the product half (800k float4)
    {
        int n4 = nd / 4;
        int threads = 256;
        int blocks = (n4 + threads - 1) / threads;
        finalize_exp_kernel<<<blocks, threads>>>((float4*)out_logprod, n4);
    }
}

// round 6
// speedup vs baseline: 2.4949x; 2.4949x over previous
#include <cuda_runtime.h>
#include <cstdint>

// D_FEAT = 64 floats = 16 float4 per row
#define D4 16
#define CHUNK_SHIFT 4   // 16 chunks of 4 floats per edge
#define CHUNK_MASK 15

__device__ int g_idx_is_32;   // 1 if edge_index is int32 on device, 0 if int64

__global__ void detect_idx_dtype_kernel(const unsigned int* __restrict__ ei_words) {
    // Interpret first 16 putative int64 entries; int64 node ids < 50000 have
    // zero high words. If any high word is nonzero, data must be int32.
    int is32 = 0;
    for (int i = 0; i < 16; i++) {
        if (ei_words[2 * i + 1] != 0u) is32 = 1;
    }
    g_idx_is_32 = is32;
}

__global__ void init_zero_kernel(float4* __restrict__ out, int n4) {
    int i = blockIdx.x * blockDim.x + threadIdx.x;
    if (i < n4) out[i] = make_float4(0.f, 0.f, 0.f, 0.f);
}

__device__ __forceinline__ void red_add_v4(float* addr, float4 v) {
    // 16B vector reduction (sm_90+). Address must be 16B-aligned.
    asm volatile("red.global.add.v4.f32 [%0], {%1, %2, %3, %4};"
                 :: "l"(addr), "f"(v.x), "f"(v.y), "f"(v.z), "f"(v.w)
                 : "memory");
}

__global__ void scatter_kernel(const float4* __restrict__ x_sum,
                               const float4* __restrict__ x_prod,
                               const void* __restrict__ edge_index,
                               float* __restrict__ out_sum,
                               float* __restrict__ out_logprod,
                               int n_edges) {
    int gid = blockIdx.x * blockDim.x + threadIdx.x;
    int e = gid >> CHUNK_SHIFT;
    if (e >= n_edges) return;
    int c = gid & CHUNK_MASK;

    int s, d;
    if (g_idx_is_32) {
        const int* ei = (const int*)edge_index;
        s = ei[e];
        d = ei[n_edges + e];
    } else {
        const long long* ei = (const long long*)edge_index;
        s = (int)ei[e];
        d = (int)ei[n_edges + e];
    }

    // Gather: 16 consecutive threads read 16 consecutive float4 = 256B row, coalesced.
    float4 ms = x_sum[s * D4 + c];
    float4 mp = x_prod[s * D4 + c];

    red_add_v4(out_sum + d * 64 + c * 4, ms);

    float4 lp = make_float4(__logf(mp.x), __logf(mp.y), __logf(mp.z), __logf(mp.w));
    red_add_v4(out_logprod + d * 64 + c * 4, lp);
}

__global__ void finalize_exp_kernel(float4* __restrict__ out_logprod, int n4) {
    int i = blockIdx.x * blockDim.x + threadIdx.x;
    if (i < n4) {
        float4 v = out_logprod[i];
        out_logprod[i] = make_float4(__expf(v.x), __expf(v.y), __expf(v.z), __expf(v.w));
    }
}

extern "C" void kernel_launch(void* const* d_in, const int* in_sizes, int n_in,
                              void* d_out, int out_size) {
    const float4* x_sum  = (const float4*)d_in[0];
    const float4* x_prod = (const float4*)d_in[1];
    const void*   ei     = d_in[2];

    const int n_nodes = in_sizes[0] / 64;        // 50000
    const int n_edges = in_sizes[2] / 2;         // 800000
    const int nd      = n_nodes * 64;            // 3.2M floats per half

    float* out_sum     = (float*)d_out;          // [N, 64]
    float* out_logprod = (float*)d_out + nd;     // [N, 64]

    // 0) detect index dtype (int32 vs int64) — deterministic for fixed input
    detect_idx_dtype_kernel<<<1, 1>>>((const unsigned int*)ei);

    // 1) zero both halves (6.4M floats = 1.6M float4)
    {
        int n4 = (2 * nd) / 4;
        int threads = 256;
        int blocks = (n4 + threads - 1) / threads;
        init_zero_kernel<<<blocks, threads>>>((float4*)d_out, n4);
    }

    // 2) scatter: one thread per (edge, 4-feature chunk) = E*16 threads
    {
        long long total = (long long)n_edges << CHUNK_SHIFT;  // 12.8M
        int threads = 256;
        int blocks = (int)((total + threads - 1) / threads);
        scatter_kernel<<<blocks, threads>>>(x_sum, x_prod, ei,
                                            out_sum, out_logprod, n_edges);
    }

    // 3) exp-finalize the product half (800k float4)
    {
        int n4 = nd / 4;
        int threads = 256;
        int blocks = (n4 + threads - 1) / threads;
        finalize_exp_kernel<<<blocks, threads>>>((float4*)out_logprod, n4);
    }
}

// round 7
// speedup vs baseline: 3.7774x; 1.5141x over previous
#include <cuda_runtime.h>
#include <cstdint>

#define N_NODES_MAX 50000
#define DEG_CAP 64
#define D4 16   // 64 floats = 16 float4 per node row

__device__ int g_idx_is_32;                       // 1 if edge_index is int32
__device__ int g_cnt[N_NODES_MAX];                // per-dst degree counters
__device__ int g_bucket[N_NODES_MAX * DEG_CAP];   // src ids per dst (12.8 MB)
__device__ int g_ovf_cnt;                         // overflow edge count
__device__ int g_ovf[800000];                     // overflow edge ids (rare path)

__global__ void detect_idx_dtype_kernel(const unsigned int* __restrict__ ei_words) {
    // int64 node ids < 50000 have zero high words; int32 data makes them nonzero.
    int is32 = 0;
    for (int i = 0; i < 16; i++)
        if (ei_words[2 * i + 1] != 0u) is32 = 1;
    g_idx_is_32 = is32;
}

__global__ void zero_counters_kernel(int n_nodes) {
    int i = blockIdx.x * blockDim.x + threadIdx.x;
    if (i < n_nodes) g_cnt[i] = 0;
    if (i == 0) g_ovf_cnt = 0;
}

__device__ __forceinline__ void load_edge(const void* edge_index, int n_edges,
                                          int e, int& s, int& d) {
    if (g_idx_is_32) {
        const int* ei = (const int*)edge_index;
        s = ei[e];
        d = ei[n_edges + e];
    } else {
        const long long* ei = (const long long*)edge_index;
        s = (int)ei[e];
        d = (int)ei[n_edges + e];
    }
}

__global__ void fill_buckets_kernel(const void* __restrict__ edge_index, int n_edges) {
    int e = blockIdx.x * blockDim.x + threadIdx.x;
    if (e >= n_edges) return;
    int s, d;
    load_edge(edge_index, n_edges, e, s, d);
    int slot = atomicAdd(&g_cnt[d], 1);
    if (slot < DEG_CAP) {
        g_bucket[d * DEG_CAP + slot] = s;
    } else {
        int p = atomicAdd(&g_ovf_cnt, 1);
        g_ovf[p] = e;
    }
}

__global__ void reduce_kernel(const float4* __restrict__ x_sum,
                              const float4* __restrict__ x_prod,
                              float4* __restrict__ out_sum,
                              float4* __restrict__ out_prod,
                              int n_nodes) {
    int gid = blockIdx.x * blockDim.x + threadIdx.x;
    int d = gid >> 4;
    if (d >= n_nodes) return;
    int c = gid & 15;

    int n = g_cnt[d];
    if (n > DEG_CAP) n = DEG_CAP;
    const int* bkt = &g_bucket[d * DEG_CAP];

    float4 as  = make_float4(0.f, 0.f, 0.f, 0.f);
    float4 alp = make_float4(0.f, 0.f, 0.f, 0.f);

    for (int i = 0; i < n; i++) {
        int s = bkt[i];                   // broadcast across the 16 lanes of this dst
        float4 ms = __ldg(&x_sum[s * D4 + c]);   // 16 lanes -> 256B coalesced
        float4 mp = __ldg(&x_prod[s * D4 + c]);
        as.x += ms.x; as.y += ms.y; as.z += ms.z; as.w += ms.w;
        alp.x += __logf(mp.x); alp.y += __logf(mp.y);
        alp.z += __logf(mp.z); alp.w += __logf(mp.w);
    }

    out_sum[d * D4 + c]  = as;
    out_prod[d * D4 + c] = make_float4(__expf(alp.x), __expf(alp.y),
                                       __expf(alp.z), __expf(alp.w));
}

// Rare path: edges beyond DEG_CAP (statistically ~never for Poisson(16)).
__global__ void overflow_kernel(const float* __restrict__ x_sum,
                                const float* __restrict__ x_prod,
                                const void* __restrict__ edge_index,
                                float* __restrict__ out_sum,
                                float* __restrict__ out_prod,
                                int n_edges) {
    int total = g_ovf_cnt;
    for (int k = blockIdx.x * blockDim.x + threadIdx.x; k < total;
         k += gridDim.x * blockDim.x) {
        int e = g_ovf[k];
        int s, d;
        load_edge(edge_index, n_edges, e, s, d);
        for (int j = 0; j < 64; j++) {
            atomicAdd(&out_sum[d * 64 + j], x_sum[s * 64 + j]);
            float m = x_prod[s * 64 + j];
            float* addr = &out_prod[d * 64 + j];
            // CAS multiply loop
            unsigned int old = __float_as_uint(*addr), assumed;
            do {
                assumed = old;
                old = atomicCAS((unsigned int*)addr, assumed,
                                __float_as_uint(__uint_as_float(assumed) * m));
            } while (old != assumed);
        }
    }
}

extern "C" void kernel_launch(void* const* d_in, const int* in_sizes, int n_in,
                              void* d_out, int out_size) {
    const float4* x_sum  = (const float4*)d_in[0];
    const float4* x_prod = (const float4*)d_in[1];
    const void*   ei     = d_in[2];

    const int n_nodes = in_sizes[0] / 64;        // 50000
    const int n_edges = in_sizes[2] / 2;         // 800000
    const int nd      = n_nodes * 64;

    float4* out_sum  = (float4*)d_out;
    float4* out_prod = (float4*)((float*)d_out + nd);

    // 0) detect index dtype + zero counters
    detect_idx_dtype_kernel<<<1, 1>>>((const unsigned int*)ei);
    zero_counters_kernel<<<(n_nodes + 255) / 256, 256>>>(n_nodes);

    // 1) bucket edges by destination
    fill_buckets_kernel<<<(n_edges + 255) / 256, 256>>>(ei, n_edges);

    // 2) per-destination register reduction, plain stores (no atomics, no init/finalize)
    {
        int total = n_nodes * 16;
        reduce_kernel<<<(total + 255) / 256, 256>>>(x_sum, x_prod,
                                                    out_sum, out_prod, n_nodes);
    }

    // 3) rare overflow fixup (normally zero iterations)
    overflow_kernel<<<4, 256>>>((const float*)d_in[0], (const float*)d_in[1], ei,
                                (float*)d_out, (float*)d_out + nd, n_edges);
}

// round 8
// speedup vs baseline: 4.3923x; 1.1628x over previous
#include <cuda_runtime.h>
#include <cstdint>

#define N_NODES_MAX 50000
#define DEG_CAP 64
#define D4 16   // 64 floats = 16 float4 per node row

__device__ int g_idx_is_32;                       // 1 if edge_index is int32
__device__ int g_cnt[N_NODES_MAX];                // per-dst degree counters
__device__ int g_bucket[N_NODES_MAX * DEG_CAP];   // src ids per dst (12.8 MB)
__device__ int g_ovf_cnt;                         // overflow edge count
__device__ int g_ovf[800000];                     // overflow edge ids (rare path)

__global__ void detect_idx_dtype_kernel(const unsigned int* __restrict__ ei_words) {
    // int64 node ids < 50000 have zero high words; int32 data makes them nonzero.
    int is32 = 0;
    for (int i = 0; i < 16; i++)
        if (ei_words[2 * i + 1] != 0u) is32 = 1;
    g_idx_is_32 = is32;
}

__global__ void zero_counters_kernel(int n_nodes) {
    int i = blockIdx.x * blockDim.x + threadIdx.x;
    if (i < n_nodes) g_cnt[i] = 0;
    if (i == 0) g_ovf_cnt = 0;
}

__device__ __forceinline__ void load_edge(const void* edge_index, int n_edges,
                                          int e, int& s, int& d) {
    if (g_idx_is_32) {
        const int* ei = (const int*)edge_index;
        s = ei[e];
        d = ei[n_edges + e];
    } else {
        const long long* ei = (const long long*)edge_index;
        s = (int)ei[e];
        d = (int)ei[n_edges + e];
    }
}

__global__ void fill_buckets_kernel(const void* __restrict__ edge_index, int n_edges) {
    int e = blockIdx.x * blockDim.x + threadIdx.x;
    if (e >= n_edges) return;
    int s, d;
    load_edge(edge_index, n_edges, e, s, d);
    int slot = atomicAdd(&g_cnt[d], 1);
    if (slot < DEG_CAP) {
        g_bucket[d * DEG_CAP + slot] = s;
    } else {
        int p = atomicAdd(&g_ovf_cnt, 1);
        g_ovf[p] = e;
    }
}

__global__ void reduce_kernel(const float4* __restrict__ x_sum,
                              const float4* __restrict__ x_prod,
                              float4* __restrict__ out_sum,
                              float4* __restrict__ out_prod,
                              int n_nodes) {
    int gid = blockIdx.x * blockDim.x + threadIdx.x;
    int d = gid >> 4;
    if (d >= n_nodes) return;
    int c = gid & 15;

    int n = g_cnt[d];
    if (n > DEG_CAP) n = DEG_CAP;
    const int* bkt = &g_bucket[d * DEG_CAP];

    float4 as = make_float4(0.f, 0.f, 0.f, 0.f);
    float4 ap = make_float4(1.f, 1.f, 1.f, 1.f);

    int i = 0;
    // Unrolled x4: one int4 bucket load -> 8 independent float4 gathers in flight.
    for (; i + 4 <= n; i += 4) {
        int4 s4 = *reinterpret_cast<const int4*>(&bkt[i]);   // 16B-aligned
        float4 ms0 = __ldg(&x_sum [s4.x * D4 + c]);
        float4 ms1 = __ldg(&x_sum [s4.y * D4 + c]);
        float4 ms2 = __ldg(&x_sum [s4.z * D4 + c]);
        float4 ms3 = __ldg(&x_sum [s4.w * D4 + c]);
        float4 mp0 = __ldg(&x_prod[s4.x * D4 + c]);
        float4 mp1 = __ldg(&x_prod[s4.y * D4 + c]);
        float4 mp2 = __ldg(&x_prod[s4.z * D4 + c]);
        float4 mp3 = __ldg(&x_prod[s4.w * D4 + c]);

        as.x += ms0.x + ms1.x + ms2.x + ms3.x;
        as.y += ms0.y + ms1.y + ms2.y + ms3.y;
        as.z += ms0.z + ms1.z + ms2.z + ms3.z;
        as.w += ms0.w + ms1.w + ms2.w + ms3.w;

        ap.x *= mp0.x * mp1.x * mp2.x * mp3.x;
        ap.y *= mp0.y * mp1.y * mp2.y * mp3.y;
        ap.z *= mp0.z * mp1.z * mp2.z * mp3.z;
        ap.w *= mp0.w * mp1.w * mp2.w * mp3.w;
    }
    for (; i < n; i++) {
        int s = bkt[i];
        float4 ms = __ldg(&x_sum [s * D4 + c]);
        float4 mp = __ldg(&x_prod[s * D4 + c]);
        as.x += ms.x; as.y += ms.y; as.z += ms.z; as.w += ms.w;
        ap.x *= mp.x; ap.y *= mp.y; ap.z *= mp.z; ap.w *= mp.w;
    }

    out_sum [d * D4 + c] = as;
    out_prod[d * D4 + c] = ap;
}

// Rare path: edges beyond DEG_CAP (statistically ~never for Poisson(16)).
__global__ void overflow_kernel(const float* __restrict__ x_sum,
                                const float* __restrict__ x_prod,
                                const void* __restrict__ edge_index,
                                float* __restrict__ out_sum,
                                float* __restrict__ out_prod,
                                int n_edges) {
    int total = g_ovf_cnt;
    for (int k = blockIdx.x * blockDim.x + threadIdx.x; k < total;
         k += gridDim.x * blockDim.x) {
        int e = g_ovf[k];
        int s, d;
        load_edge(edge_index, n_edges, e, s, d);
        for (int j = 0; j < 64; j++) {
            atomicAdd(&out_sum[d * 64 + j], x_sum[s * 64 + j]);
            float m = x_prod[s * 64 + j];
            float* addr = &out_prod[d * 64 + j];
            unsigned int old = __float_as_uint(*addr), assumed;
            do {
                assumed = old;
                old = atomicCAS((unsigned int*)addr, assumed,
                                __float_as_uint(__uint_as_float(assumed) * m));
            } while (old != assumed);
        }
    }
}

extern "C" void kernel_launch(void* const* d_in, const int* in_sizes, int n_in,
                              void* d_out, int out_size) {
    const float4* x_sum  = (const float4*)d_in[0];
    const float4* x_prod = (const float4*)d_in[1];
    const void*   ei     = d_in[2];

    const int n_nodes = in_sizes[0] / 64;        // 50000
    const int n_edges = in_sizes[2] / 2;         // 800000
    const int nd      = n_nodes * 64;

    float4* out_sum  = (float4*)d_out;
    float4* out_prod = (float4*)((float*)d_out + nd);

    // 0) detect index dtype + zero counters
    detect_idx_dtype_kernel<<<1, 1>>>((const unsigned int*)ei);
    zero_counters_kernel<<<(n_nodes + 255) / 256, 256>>>(n_nodes);

    // 1) bucket edges by destination
    fill_buckets_kernel<<<(n_edges + 255) / 256, 256>>>(ei, n_edges);

    // 2) per-destination register reduction, plain stores (no atomics, no init/finalize)
    {
        int total = n_nodes * 16;
        reduce_kernel<<<(total + 255) / 256, 256>>>(x_sum, x_prod,
                                                    out_sum, out_prod, n_nodes);
    }

    // 3) rare overflow fixup (normally zero iterations)
    overflow_kernel<<<4, 256>>>((const float*)d_in[0], (const float*)d_in[1], ei,
                                (float*)d_out, (float*)d_out + nd, n_edges);
}

// round 9
// speedup vs baseline: 4.5978x; 1.0468x over previous
#include <cuda_runtime.h>
#include <cstdint>

#define N_NODES_MAX 50000
#define DEG_CAP 64
#define D4 16   // 64 floats = 16 float4 per node row

__device__ int g_cnt[N_NODES_MAX];                // per-dst degree counters
__device__ int g_bucket[N_NODES_MAX * DEG_CAP];   // src ids per dst (12.8 MB)
__device__ int g_ovf_cnt;                         // overflow edge count
__device__ int g_ovf[800000];                     // overflow edge ids (rare path)

// Inline dtype detect: interpret first 8 putative int64 entries; true int64
// node ids (< 50000) have zero high words. Random int32 ids make them nonzero.
// Same addresses for every thread -> broadcast loads, negligible cost.
__device__ __forceinline__ int detect_is32(const unsigned int* __restrict__ w) {
    int is32 = 0;
#pragma unroll
    for (int i = 0; i < 8; i++) is32 |= (w[2 * i + 1] != 0u);
    return is32;
}

__device__ __forceinline__ void load_edge(const void* edge_index, int is32,
                                          int n_edges, int e, int& s, int& d) {
    if (is32) {
        const int* ei = (const int*)edge_index;
        s = ei[e];
        d = ei[n_edges + e];
    } else {
        const long long* ei = (const long long*)edge_index;
        s = (int)ei[e];
        d = (int)ei[n_edges + e];
    }
}

__global__ void zero_counters_kernel(int n_nodes) {
    int i = blockIdx.x * blockDim.x + threadIdx.x;
    if (i < n_nodes) g_cnt[i] = 0;
    if (i == 0) g_ovf_cnt = 0;
}

__global__ void fill_buckets_kernel(const void* __restrict__ edge_index, int n_edges) {
    int e = blockIdx.x * blockDim.x + threadIdx.x;
    if (e >= n_edges) return;
    int is32 = detect_is32((const unsigned int*)edge_index);
    int s, d;
    load_edge(edge_index, is32, n_edges, e, s, d);
    int slot = atomicAdd(&g_cnt[d], 1);
    if (slot < DEG_CAP) {
        g_bucket[d * DEG_CAP + slot] = s;
    } else {
        int p = atomicAdd(&g_ovf_cnt, 1);
        g_ovf[p] = e;
    }
}

__global__ void reduce_kernel(const float4* __restrict__ x_sum,
                              const float4* __restrict__ x_prod,
                              float4* __restrict__ out_sum,
                              float4* __restrict__ out_prod,
                              int n_nodes) {
    int gid = blockIdx.x * blockDim.x + threadIdx.x;
    int d = gid >> 4;
    if (d >= n_nodes) return;
    int c = gid & 15;

    int n = g_cnt[d];
    if (n > DEG_CAP) n = DEG_CAP;
    const int* bkt = &g_bucket[d * DEG_CAP];

    float4 as = make_float4(0.f, 0.f, 0.f, 0.f);
    float4 ap = make_float4(1.f, 1.f, 1.f, 1.f);

    int i = 0;
    // Unrolled x4: one int4 bucket load -> 8 independent float4 gathers in flight.
    for (; i + 4 <= n; i += 4) {
        int4 s4 = *reinterpret_cast<const int4*>(&bkt[i]);   // 16B-aligned
        float4 ms0 = __ldg(&x_sum [s4.x * D4 + c]);
        float4 ms1 = __ldg(&x_sum [s4.y * D4 + c]);
        float4 ms2 = __ldg(&x_sum [s4.z * D4 + c]);
        float4 ms3 = __ldg(&x_sum [s4.w * D4 + c]);
        float4 mp0 = __ldg(&x_prod[s4.x * D4 + c]);
        float4 mp1 = __ldg(&x_prod[s4.y * D4 + c]);
        float4 mp2 = __ldg(&x_prod[s4.z * D4 + c]);
        float4 mp3 = __ldg(&x_prod[s4.w * D4 + c]);

        as.x += ms0.x + ms1.x + ms2.x + ms3.x;
        as.y += ms0.y + ms1.y + ms2.y + ms3.y;
        as.z += ms0.z + ms1.z + ms2.z + ms3.z;
        as.w += ms0.w + ms1.w + ms2.w + ms3.w;

        ap.x *= mp0.x * mp1.x * mp2.x * mp3.x;
        ap.y *= mp0.y * mp1.y * mp2.y * mp3.y;
        ap.z *= mp0.z * mp1.z * mp2.z * mp3.z;
        ap.w *= mp0.w * mp1.w * mp2.w * mp3.w;
    }
    for (; i < n; i++) {
        int s = bkt[i];
        float4 ms = __ldg(&x_sum [s * D4 + c]);
        float4 mp = __ldg(&x_prod[s * D4 + c]);
        as.x += ms.x; as.y += ms.y; as.z += ms.z; as.w += ms.w;
        ap.x *= mp.x; ap.y *= mp.y; ap.z *= mp.z; ap.w *= mp.w;
    }

    out_sum [d * D4 + c] = as;
    out_prod[d * D4 + c] = ap;
}

// Rare path: edges beyond DEG_CAP (statistically ~never for avg degree 16).
__global__ void overflow_kernel(const float* __restrict__ x_sum,
                                const float* __restrict__ x_prod,
                                const void* __restrict__ edge_index,
                                float* __restrict__ out_sum,
                                float* __restrict__ out_prod,
                                int n_edges) {
    int total = g_ovf_cnt;
    if (total == 0) return;
    int is32 = detect_is32((const unsigned int*)edge_index);
    for (int k = blockIdx.x * blockDim.x + threadIdx.x; k < total;
         k += gridDim.x * blockDim.x) {
        int e = g_ovf[k];
        int s, d;
        load_edge(edge_index, is32, n_edges, e, s, d);
        for (int j = 0; j < 64; j++) {
            atomicAdd(&out_sum[d * 64 + j], x_sum[s * 64 + j]);
            float m = x_prod[s * 64 + j];
            float* addr = &out_prod[d * 64 + j];
            unsigned int old = __float_as_uint(*addr), assumed;
            do {
                assumed = old;
                old = atomicCAS((unsigned int*)addr, assumed,
                                __float_as_uint(__uint_as_float(assumed) * m));
            } while (old != assumed);
        }
    }
}

extern "C" void kernel_launch(void* const* d_in, const int* in_sizes, int n_in,
                              void* d_out, int out_size) {
    const float4* x_sum  = (const float4*)d_in[0];
    const float4* x_prod = (const float4*)d_in[1];
    const void*   ei     = d_in[2];

    const int n_nodes = in_sizes[0] / 64;        // 50000
    const int n_edges = in_sizes[2] / 2;         // 800000
    const int nd      = n_nodes * 64;

    float4* out_sum  = (float4*)d_out;
    float4* out_prod = (float4*)((float*)d_out + nd);

    // 1) zero counters (+ overflow counter)
    zero_counters_kernel<<<(n_nodes + 255) / 256, 256>>>(n_nodes);

    // 2) bucket edges by destination (dtype detected inline)
    fill_buckets_kernel<<<(n_edges + 255) / 256, 256>>>(ei, n_edges);

    // 3) per-destination register reduction, plain stores (no atomics, no init/finalize)
    {
        int total = n_nodes * 16;
        reduce_kernel<<<(total + 255) / 256, 256>>>(x_sum, x_prod,
                                                    out_sum, out_prod, n_nodes);
    }

    // 4) rare overflow fixup (normally zero iterations)
    overflow_kernel<<<1, 256>>>((const float*)d_in[0], (const float*)d_in[1], ei,
                                (float*)d_out, (float*)d_out + nd, n_edges);
}